// round 8
// baseline (speedup 1.0000x reference)
#include <cuda_runtime.h>

// SNN XOR net — single-wave persistent round.
// Body bit-identical to R7 (FSET spike; FFMA-imm reset; STG.128; 4 elem/group).
// Launch: exactly 1024 blocks x 128 threads + 30KB ballast -> all CTAs resident
// in ONE wave (7 blocks/SM cap = 1036 >= 1024). Each thread grid-strides over
// 2 groups of 4 elements: no wave transition, one ramp, weights amortized.

#define T_STEPS 20
#define BETA 0.9f
#define THR 1.0f

__device__ __forceinline__ float fset_gt(float a, float b) {
    float d;
    asm("set.gt.f32.f32 %0, %1, %2;" : "=f"(d) : "f"(a), "f"(b));
    return d;  // 1.0f if a > b else 0.0f
}

__global__ void __launch_bounds__(128) snn_xornet_kernel(
    const float* __restrict__ x,    // [B,2]
    const float* __restrict__ w1,   // [4,2]
    const float* __restrict__ w2,   // [1,4]
    float* __restrict__ out,        // [T,B]
    int B)
{
    extern __shared__ float smem_ballast[];   // occupancy ballast, never used
    if (B < 0) smem_ballast[threadIdx.x] = 1.0f;  // never executes

    float w1r[4][2];
#pragma unroll
    for (int h = 0; h < 4; h++) {
        w1r[h][0] = __ldg(&w1[2 * h + 0]);
        w1r[h][1] = __ldg(&w1[2 * h + 1]);
    }
    float w2r[4];
#pragma unroll
    for (int h = 0; h < 4; h++) w2r[h] = __ldg(&w2[h]);

    const int groups = B >> 2;               // total groups of 4 elements
    const int stride = gridDim.x * blockDim.x;
    const int Bq = B >> 2;
    float4* out4 = reinterpret_cast<float4*>(out);

#pragma unroll 1
    for (int i = blockIdx.x * blockDim.x + threadIdx.x; i < groups; i += stride) {
        // x for 4 batch elements: 8 contiguous floats
        const float4 xa = reinterpret_cast<const float4*>(x)[2 * i + 0];
        const float4 xb = reinterpret_cast<const float4*>(x)[2 * i + 1];
        const float xs[4][2] = {{xa.x, xa.y}, {xa.z, xa.w}, {xb.x, xb.y}, {xb.z, xb.w}};

        // cur = x @ w1^T (identical rounding to all passing kernels)
        float cur[4][4];
#pragma unroll
        for (int j = 0; j < 4; j++)
#pragma unroll
            for (int h = 0; h < 4; h++)
                cur[j][h] = fmaf(xs[j][0], w1r[h][0], xs[j][1] * w1r[h][1]);

        float m1[4][4], s1[4][4];
        float m2[4], s2[4];
#pragma unroll
        for (int j = 0; j < 4; j++) {
            m2[j] = 0.0f; s2[j] = 0.0f;
#pragma unroll
            for (int h = 0; h < 4; h++) { m1[j][h] = 0.0f; s1[j][h] = 0.0f; }
        }

        float4* optr = out4 + i;

#pragma unroll
        for (int t = 0; t < T_STEPS; t++) {
            float o[4];
#pragma unroll
            for (int j = 0; j < 4; j++) {
                float acc = 0.0f;
#pragma unroll
                for (int h = 0; h < 4; h++) {
                    float m = fmaf(BETA, m1[j][h], cur[j][h]);
                    m = fmaf(s1[j][h], -1.0f, m);     // == m - s (bit-exact), FFMA-imm
                    m1[j][h] = m;
                    const float sp = fset_gt(m, THR); // FSET: 1.0/0.0
                    s1[j][h] = sp;
                    acc = fmaf(sp, w2r[h], acc);      // exact: +w2 or +0
                }
                float mo = fmaf(BETA, m2[j], acc);
                mo = fmaf(s2[j], -1.0f, mo);          // == mo - s2 (bit-exact)
                m2[j] = mo;
                const float so = fset_gt(mo, THR);
                s2[j] = so;
                o[j] = so;
            }
            float4 v;
            v.x = o[0]; v.y = o[1]; v.z = o[2]; v.w = o[3];
            *optr = v;
            optr += Bq;                                // pointer bump, no IMAD
        }
    }
}

extern "C" void kernel_launch(void* const* d_in, const int* in_sizes, int n_in,
                              void* d_out, int out_size) {
    const float* x  = (const float*)d_in[0];   // [B,2]
    const float* w1 = (const float*)d_in[1];   // [4,2]
    const float* w2 = (const float*)d_in[2];   // [1,4]
    float* out = (float*)d_out;                // [T,B,1]

    const int B = in_sizes[0] / 2;
    const int threads = 128;
    const int blocks = 1024;                   // <= 1036 resident: ONE wave
    const size_t ballast = 30 * 1024;          // pins 7 blocks/SM
    snn_xornet_kernel<<<blocks, threads, ballast>>>(x, w1, w2, out, B);
}

// round 10
// speedup vs baseline: 1.0491x; 1.0491x over previous
#include <cuda_runtime.h>

// SNN XOR net — FFMA-imm throughput round (resubmit; R9 bench was an infra
// failure, not a kernel failure).
// Identical arithmetic to R7 (best kernel: 17.18us). Two changes:
//  1. beta-multiplies written fmaf(m, 0.9f, cur) so 0.9 encodes as the src1
//     IMMEDIATE (FFMA-imm rt_SMSP=1 vs 2 for 3-reg) — bit-identical (commute).
//     Reset fmaf(s, -1.0f, m) already imm-form.
//  2. Bq compile-time (B=2^20 template) so store addressing folds to immediates.
// Launch shape = R7: block 128, grid 2048, 30KB ballast (7 blocks/SM, 98.8% fill).

#define T_STEPS 20
#define THR 1.0f

__device__ __forceinline__ float fset_gt(float a, float b) {
    float d;
    asm("set.gt.f32.f32 %0, %1, %2;" : "=f"(d) : "f"(a), "f"(b));
    return d;  // 1.0f if a > b else 0.0f
}

template <int BQ>   // BQ = B/4 groups; BQ==0 means runtime B
__global__ void __launch_bounds__(128) snn_xornet_kernel(
    const float* __restrict__ x,    // [B,2]
    const float* __restrict__ w1,   // [4,2]
    const float* __restrict__ w2,   // [1,4]
    float* __restrict__ out,        // [T,B]
    int B)
{
    extern __shared__ float smem_ballast[];   // occupancy ballast, never used
    const int i = blockIdx.x * blockDim.x + threadIdx.x;  // group of 4 elems
    if (i * 4 >= B) return;
    if (B < 0) smem_ballast[threadIdx.x] = (float)i;      // never executes

    float w1r[4][2];
#pragma unroll
    for (int h = 0; h < 4; h++) {
        w1r[h][0] = __ldg(&w1[2 * h + 0]);
        w1r[h][1] = __ldg(&w1[2 * h + 1]);
    }
    float w2r[4];
#pragma unroll
    for (int h = 0; h < 4; h++) w2r[h] = __ldg(&w2[h]);

    const float4 xa = reinterpret_cast<const float4*>(x)[2 * i + 0];
    const float4 xb = reinterpret_cast<const float4*>(x)[2 * i + 1];
    const float xs[4][2] = {{xa.x, xa.y}, {xa.z, xa.w}, {xb.x, xb.y}, {xb.z, xb.w}};

    // cur = x @ w1^T (identical rounding to all passing kernels)
    float cur[4][4];
#pragma unroll
    for (int j = 0; j < 4; j++)
#pragma unroll
        for (int h = 0; h < 4; h++)
            cur[j][h] = fmaf(xs[j][0], w1r[h][0], xs[j][1] * w1r[h][1]);

    float m1[4][4], s1[4][4];
    float m2[4], s2[4];
#pragma unroll
    for (int j = 0; j < 4; j++) {
        m2[j] = 0.0f; s2[j] = 0.0f;
#pragma unroll
        for (int h = 0; h < 4; h++) { m1[j][h] = 0.0f; s1[j][h] = 0.0f; }
    }

    const int bq = (BQ > 0) ? BQ : (B >> 2);
    float4* out4 = reinterpret_cast<float4*>(out);

#pragma unroll
    for (int t = 0; t < T_STEPS; t++) {
        float o[4];
#pragma unroll
        for (int j = 0; j < 4; j++) {
            float acc = 0.0f;
#pragma unroll
            for (int h = 0; h < 4; h++) {
                // beta as src1 IMMEDIATE (commuted, bit-identical): FFMA-imm rt 1
                float m = fmaf(m1[j][h], 0.9f, cur[j][h]);
                m = fmaf(s1[j][h], -1.0f, m);        // == m - s (bit-exact), imm
                m1[j][h] = m;
                const float sp = fset_gt(m, THR);    // FSET: 1.0/0.0
                s1[j][h] = sp;
                acc = fmaf(sp, w2r[h], acc);         // exact: +w2 or +0
            }
            float mo = fmaf(m2[j], 0.9f, acc);       // imm-form
            mo = fmaf(s2[j], -1.0f, mo);             // == mo - s2 (bit-exact)
            m2[j] = mo;
            const float so = fset_gt(mo, THR);
            s2[j] = so;
            o[j] = so;
        }
        float4 v;
        v.x = o[0]; v.y = o[1]; v.z = o[2]; v.w = o[3];
        out4[(size_t)t * bq + i] = v;                // bq constexpr in hot path
    }
}

extern "C" void kernel_launch(void* const* d_in, const int* in_sizes, int n_in,
                              void* d_out, int out_size) {
    const float* x  = (const float*)d_in[0];   // [B,2]
    const float* w1 = (const float*)d_in[1];   // [4,2]
    const float* w2 = (const float*)d_in[2];   // [1,4]
    float* out = (float*)d_out;                // [T,B,1]

    const int B = in_sizes[0] / 2;
    const int threads = 128;
    const int blocks = (B / 4 + threads - 1) / threads;
    const size_t ballast = 30 * 1024;          // 7 blocks/SM -> 98.8% fill
    if (B == 1048576) {
        snn_xornet_kernel<262144><<<blocks, threads, ballast>>>(x, w1, w2, out, B);
    } else {
        snn_xornet_kernel<0><<<blocks, threads, ballast>>>(x, w1, w2, out, B);
    }
}

// round 11
// speedup vs baseline: 1.0671x; 1.0172x over previous
#include <cuda_runtime.h>

// SNN XOR net — streaming-store round.
// Arithmetic byte-identical to R10 (best wall 18.91us): FSET spike 1.0/0.0,
// beta as FFMA src1-immediate, reset FFMA-imm, acc fma chain in h order.
// Changes:
//  1. Output stores use st.global.cs.v4 (evict-first streaming): output is
//     write-once never-read; shortens LSU/L2 write-queue residency.
//  2. float4 built directly per j (no o[4] temp -> fewer alu MOVs).
//  3. __launch_bounds__(128, 7) pins regs <= 64 (7 blocks/SM with ballast).
// Launch: block 128, grid 2048, 30KB ballast -> 7 blocks/SM, 1.98 waves, 98.8% fill.

#define T_STEPS 20
#define THR 1.0f

__device__ __forceinline__ float fset_gt(float a, float b) {
    float d;
    asm("set.gt.f32.f32 %0, %1, %2;" : "=f"(d) : "f"(a), "f"(b));
    return d;  // 1.0f if a > b else 0.0f
}

__device__ __forceinline__ void stg_cs_v4(float4* p, float4 v) {
    asm volatile("st.global.cs.v4.f32 [%0], {%1, %2, %3, %4};"
                 :: "l"(p), "f"(v.x), "f"(v.y), "f"(v.z), "f"(v.w) : "memory");
}

template <int BQ>   // BQ = B/4 groups; BQ==0 means runtime B
__global__ void __launch_bounds__(128, 7) snn_xornet_kernel(
    const float* __restrict__ x,    // [B,2]
    const float* __restrict__ w1,   // [4,2]
    const float* __restrict__ w2,   // [1,4]
    float* __restrict__ out,        // [T,B]
    int B)
{
    extern __shared__ float smem_ballast[];   // occupancy ballast, never used
    const int i = blockIdx.x * blockDim.x + threadIdx.x;  // group of 4 elems
    if (i * 4 >= B) return;
    if (B < 0) smem_ballast[threadIdx.x] = (float)i;      // never executes

    float w1r[4][2];
#pragma unroll
    for (int h = 0; h < 4; h++) {
        w1r[h][0] = __ldg(&w1[2 * h + 0]);
        w1r[h][1] = __ldg(&w1[2 * h + 1]);
    }
    float w2r[4];
#pragma unroll
    for (int h = 0; h < 4; h++) w2r[h] = __ldg(&w2[h]);

    const float4 xa = reinterpret_cast<const float4*>(x)[2 * i + 0];
    const float4 xb = reinterpret_cast<const float4*>(x)[2 * i + 1];
    const float xs[4][2] = {{xa.x, xa.y}, {xa.z, xa.w}, {xb.x, xb.y}, {xb.z, xb.w}};

    // cur = x @ w1^T (identical rounding to all passing kernels)
    float cur[4][4];
#pragma unroll
    for (int j = 0; j < 4; j++)
#pragma unroll
        for (int h = 0; h < 4; h++)
            cur[j][h] = fmaf(xs[j][0], w1r[h][0], xs[j][1] * w1r[h][1]);

    float m1[4][4], s1[4][4];
    float m2[4], s2[4];
#pragma unroll
    for (int j = 0; j < 4; j++) {
        m2[j] = 0.0f; s2[j] = 0.0f;
#pragma unroll
        for (int h = 0; h < 4; h++) { m1[j][h] = 0.0f; s1[j][h] = 0.0f; }
    }

    const int bq = (BQ > 0) ? BQ : (B >> 2);
    float4* out4 = reinterpret_cast<float4*>(out);

#pragma unroll
    for (int t = 0; t < T_STEPS; t++) {
        float4 v;
#pragma unroll
        for (int j = 0; j < 4; j++) {
            float acc = 0.0f;
#pragma unroll
            for (int h = 0; h < 4; h++) {
                // beta as src1 IMMEDIATE (commuted, bit-identical): FFMA-imm rt 1
                float m = fmaf(m1[j][h], 0.9f, cur[j][h]);
                m = fmaf(s1[j][h], -1.0f, m);        // == m - s (bit-exact), imm
                m1[j][h] = m;
                const float sp = fset_gt(m, THR);    // FSET: 1.0/0.0
                s1[j][h] = sp;
                acc = fmaf(sp, w2r[h], acc);         // exact: +w2 or +0
            }
            float mo = fmaf(m2[j], 0.9f, acc);       // imm-form
            mo = fmaf(s2[j], -1.0f, mo);             // == mo - s2 (bit-exact)
            m2[j] = mo;
            const float so = fset_gt(mo, THR);
            s2[j] = so;
            if (j == 0) v.x = so;
            else if (j == 1) v.y = so;
            else if (j == 2) v.z = so;
            else v.w = so;
        }
        stg_cs_v4(out4 + (size_t)t * bq + i, v);     // streaming STG.128
    }
}

extern "C" void kernel_launch(void* const* d_in, const int* in_sizes, int n_in,
                              void* d_out, int out_size) {
    const float* x  = (const float*)d_in[0];   // [B,2]
    const float* w1 = (const float*)d_in[1];   // [4,2]
    const float* w2 = (const float*)d_in[2];   // [1,4]
    float* out = (float*)d_out;                // [T,B,1]

    const int B = in_sizes[0] / 2;
    const int threads = 128;
    const int blocks = (B / 4 + threads - 1) / threads;
    const size_t ballast = 30 * 1024;          // 7 blocks/SM -> 98.8% fill
    if (B == 1048576) {
        snn_xornet_kernel<262144><<<blocks, threads, ballast>>>(x, w1, w2, out, B);
    } else {
        snn_xornet_kernel<0><<<blocks, threads, ballast>>>(x, w1, w2, out, B);
    }
}